// round 2
// baseline (speedup 1.0000x reference)
#include <cuda_runtime.h>
#include <cstdint>

#define NN      100000
#define TT      4
#define EE      400000
#define TE      1600000
#define CC      2
#define LL      2
#define WIN     128
#define DD      64
#define CD      128
#define NCLS    16
#define MM      10000

// ---------------- device scratch (static; no runtime allocation) ------------
__device__ float    g_Xp[NN * CD];      // per-channel projected input, interleaved [N][C*D]
__device__ float    g_H0[NN * CD];      // layer-0 output
__device__ float    g_H1[NN * CD];      // layer-1 output
__device__ unsigned g_pc[TE];           // packed col | (type<<20)
__device__ float    g_w [TE];           // raw edge weights (CSR order)
__device__ int      g_cnt[NN];          // per-destination degree
__device__ int      g_off[NN + 1];      // CSR offsets
__device__ int      g_cur[NN];          // scatter cursors
__device__ int      g_bsum[256];        // scan partials
__device__ int      g_boff[256];
__device__ float    g_filt[LL * CC * TT];

// ---------------- tiny softmax over edge types ------------------------------
__global__ void k_filt(const float* __restrict__ cw) {
    int i = threadIdx.x;              // (l,c) pair
    if (i < LL * CC) {
        const float* p = cw + i * TT;
        float m = p[0];
        for (int t = 1; t < TT; t++) m = fmaxf(m, p[t]);
        float e[TT]; float s = 0.f;
        for (int t = 0; t < TT; t++) { e[t] = __expf(p[t] - m); s += e[t]; }
        float inv = 1.f / s;
        for (int t = 0; t < TT; t++) g_filt[i * TT + t] = e[t] * inv;
    }
}

// ---------------- CSR build --------------------------------------------------
__global__ void k_zero() {
    int i = blockIdx.x * blockDim.x + threadIdx.x;
    if (i < NN) g_cnt[i] = 0;
}

__global__ void k_hist(const int* __restrict__ ei) {
    int idx = blockIdx.x * blockDim.x + threadIdx.x;
    if (idx >= TE) return;
    int t = idx / EE;
    int e = idx - t * EE;
    int dst = ei[t * 2 * EE + e];
    atomicAdd(&g_cnt[dst], 1);
}

#define SCHUNK 512
#define SNB    196            // ceil(100000/512)

__global__ void k_scan1() {
    __shared__ int s[SCHUNK];
    int tid = threadIdx.x;
    int i = blockIdx.x * SCHUNK + tid;
    int v = (i < NN) ? g_cnt[i] : 0;
    s[tid] = v;
    __syncthreads();
    for (int o = 1; o < SCHUNK; o <<= 1) {
        int t = (tid >= o) ? s[tid - o] : 0;
        __syncthreads();
        s[tid] += t;
        __syncthreads();
    }
    if (i < NN) g_off[i] = s[tid] - v;               // chunk-local exclusive
    if (tid == SCHUNK - 1) g_bsum[blockIdx.x] = s[tid];
}

__global__ void k_scan2() {
    __shared__ int s[256];
    int tid = threadIdx.x;
    int v = (tid < SNB) ? g_bsum[tid] : 0;
    s[tid] = v;
    __syncthreads();
    for (int o = 1; o < 256; o <<= 1) {
        int t = (tid >= o) ? s[tid - o] : 0;
        __syncthreads();
        s[tid] += t;
        __syncthreads();
    }
    if (tid < SNB) g_boff[tid] = s[tid] - v;         // exclusive chunk bases
}

__global__ void k_scan3() {
    int tid = threadIdx.x;
    int i = blockIdx.x * SCHUNK + tid;
    if (i < NN) {
        int o = g_off[i] + g_boff[blockIdx.x];
        g_off[i] = o;
        g_cur[i] = o;
    }
    if (blockIdx.x == 0 && tid == 0) g_off[NN] = TE;
}

__global__ void k_scatter(const int* __restrict__ ei, const float* __restrict__ ev) {
    int idx = blockIdx.x * blockDim.x + threadIdx.x;
    if (idx >= TE) return;
    int t = idx / EE;
    int e = idx - t * EE;
    int dst = ei[t * 2 * EE + e];
    int col = ei[t * 2 * EE + EE + e];
    int pos = atomicAdd(&g_cur[dst], 1);
    g_pc[pos] = (unsigned)col | ((unsigned)t << 20);
    g_w[pos]  = ev[idx];
}

// ---------------- input projection: Xp[n][c*64+d] = X[n] @ Ws[c][:,d] --------
#define GBN 32
__global__ void __launch_bounds__(128) k_gemm(const float* __restrict__ X,
                                              const float* __restrict__ Ws) {
    __shared__ float Xs[GBN][WIN];
    int tid = threadIdx.x;
    int n0 = blockIdx.x * GBN;
    for (int idx = tid; idx < GBN * WIN; idx += 128)
        Xs[idx >> 7][idx & 127] = X[(n0 + (idx >> 7)) * WIN + (idx & 127)];
    __syncthreads();

    int c = tid >> 6, d = tid & 63;
    const float* wp = Ws + c * (WIN * DD) + d;     // Ws[c][f][d], stride DD in f
    float acc[GBN];
#pragma unroll
    for (int i = 0; i < GBN; i++) acc[i] = 0.f;

    for (int f = 0; f < WIN; f += 4) {
        float w0 = wp[(f + 0) * DD];
        float w1 = wp[(f + 1) * DD];
        float w2 = wp[(f + 2) * DD];
        float w3 = wp[(f + 3) * DD];
#pragma unroll
        for (int i = 0; i < GBN; i++) {
            float4 x = *(const float4*)&Xs[i][f];
            acc[i] += x.x * w0 + x.y * w1 + x.z * w2 + x.w * w3;
        }
    }
#pragma unroll
    for (int i = 0; i < GBN; i++)
        g_Xp[(n0 + i) * CD + tid] = acc[i];
}

// ---------------- SpMM: warp per destination, both channels fused ------------
// NOTE: in/out arrays selected by DEVICE-side symbol reference (never pass
// __device__ globals as kernel args from host — that passes the host shadow
// address, which on GB300/ATS is silently readable and full of zeros).
__global__ void __launch_bounds__(256) k_spmm(int layer) {
    const float* __restrict__ Hin  = (layer == 0) ? g_Xp : g_H0;
    float* __restrict__       Hout = (layer == 0) ? g_H0 : g_H1;

    __shared__ float fs[CC * TT];
    int tid = threadIdx.x;
    if (tid < CC * TT) fs[tid] = g_filt[layer * CC * TT + tid];
    __syncthreads();

    int wid = (blockIdx.x * blockDim.x + tid) >> 5;
    if (wid >= NN) return;
    int lane = tid & 31;
    int c = lane >> 4;                 // lanes 0-15 channel 0, 16-31 channel 1
    const float* fc = fs + c * TT;
    int off4 = lane * 4;               // this lane's 4 floats within the 128-row

    int i   = g_off[wid];
    int end = g_off[wid + 1];
    float ax = 0.f, ay = 0.f, az = 0.f, aw = 0.f;

    for (; i + 2 <= end; i += 2) {
        unsigned p0 = g_pc[i],     p1 = g_pc[i + 1];
        float    w0 = g_w[i],      w1 = g_w[i + 1];
        const float4 h0 = *(const float4*)(Hin + (size_t)(p0 & 0xFFFFFu) * CD + off4);
        const float4 h1 = *(const float4*)(Hin + (size_t)(p1 & 0xFFFFFu) * CD + off4);
        float f0 = w0 * fc[p0 >> 20];
        float f1 = w1 * fc[p1 >> 20];
        ax += f0 * h0.x + f1 * h1.x;
        ay += f0 * h0.y + f1 * h1.y;
        az += f0 * h0.z + f1 * h1.z;
        aw += f0 * h0.w + f1 * h1.w;
    }
    if (i < end) {
        unsigned p0 = g_pc[i];
        float    w0 = g_w[i];
        const float4 h0 = *(const float4*)(Hin + (size_t)(p0 & 0xFFFFFu) * CD + off4);
        float f0 = w0 * fc[p0 >> 20];
        ax += f0 * h0.x; ay += f0 * h0.y; az += f0 * h0.z; aw += f0 * h0.w;
    }
    float4 out = make_float4(ax, ay, az, aw);
    *(float4*)(Hout + (size_t)wid * CD + off4) = out;
}

// ---------------- fused tail at target nodes ---------------------------------
#define TGT 8
__global__ void __launch_bounds__(128) k_tail(const int* __restrict__ targets,
                                              const float* __restrict__ lin1_w,
                                              const float* __restrict__ lin1_b,
                                              const float* __restrict__ lin_w,
                                              const float* __restrict__ lin_b,
                                              float* __restrict__ out) {
    __shared__ float hc[TGT][CD];
    __shared__ float hs[TGT][DD];
    __shared__ int   tg[TGT];
    int tid = threadIdx.x;
    int m0 = blockIdx.x * TGT;
    if (tid < TGT) tg[tid] = targets[m0 + tid];
    __syncthreads();

    for (int idx = tid; idx < TGT * CD; idx += 128) {
        int t = idx >> 7, k = idx & 127;
        size_t p = (size_t)tg[t] * CD + k;
        float v = 0.5f * g_Xp[p] + 0.5f * g_H1[p];
        hc[t][k] = v > 0.f ? v : 0.f;
    }
    __syncthreads();

    // lin1: 8 targets x 64 outputs, each thread does 4 targets at column d
    int half = tid >> 6;
    int d = tid & 63;
    int t0 = half * 4;
    float a0 = lin1_b[d], a1 = a0, a2 = a0, a3 = a0;
    for (int k = 0; k < CD; k++) {
        float w = lin1_w[k * DD + d];
        a0 += hc[t0 + 0][k] * w;
        a1 += hc[t0 + 1][k] * w;
        a2 += hc[t0 + 2][k] * w;
        a3 += hc[t0 + 3][k] * w;
    }
    hs[t0 + 0][d] = a0;
    hs[t0 + 1][d] = a1;
    hs[t0 + 2][d] = a2;
    hs[t0 + 3][d] = a3;
    __syncthreads();

    // head: 8 targets x 16 classes = 128 outputs, one per thread
    int t = tid >> 4, j = tid & 15;
    float o = lin_b[j];
    for (int dd = 0; dd < DD; dd++)
        o += hs[t][dd] * lin_w[dd * NCLS + j];
    out[(size_t)(m0 + t) * NCLS + j] = o;
}

// ---------------- launcher ---------------------------------------------------
extern "C" void kernel_launch(void* const* d_in, const int* in_sizes, int n_in,
                              void* d_out, int out_size) {
    const float* X      = (const float*)d_in[0];
    const float* ev     = (const float*)d_in[1];
    const float* cw     = (const float*)d_in[2];
    const float* lin1_w = (const float*)d_in[4];
    const float* lin1_b = (const float*)d_in[5];
    const float* lin_w  = (const float*)d_in[6];
    const float* lin_b  = (const float*)d_in[7];
    const int*   ei     = (const int*)d_in[8];
    const int*   tgt    = (const int*)d_in[9];
    const float* Ws     = (const float*)d_in[3];
    float* out          = (float*)d_out;

    k_filt<<<1, 32>>>(cw);
    k_zero<<<(NN + 255) / 256, 256>>>();
    k_hist<<<(TE + 255) / 256, 256>>>(ei);
    k_scan1<<<SNB, SCHUNK>>>();
    k_scan2<<<1, 256>>>();
    k_scan3<<<SNB, SCHUNK>>>();
    k_scatter<<<(TE + 255) / 256, 256>>>(ei, ev);

    k_gemm<<<NN / GBN, 128>>>(X, Ws);

    k_spmm<<<(NN * 32 + 255) / 256, 256>>>(0);
    k_spmm<<<(NN * 32 + 255) / 256, 256>>>(1);

    k_tail<<<MM / TGT, 128>>>(tgt, lin1_w, lin1_b, lin_w, lin_b, out);
}

// round 3
// speedup vs baseline: 1.1716x; 1.1716x over previous
#include <cuda_runtime.h>
#include <cuda_fp16.h>
#include <cstdint>

#define NN      100000
#define TT      4
#define EE      400000
#define TE      1600000
#define CC      2
#define LL      2
#define WIN     128
#define DD      64
#define CD      128
#define NCLS    16
#define MM      10000

// ---------------- device scratch (static; no runtime allocation) ------------
__device__ float    g_Xp[NN * CD];      // fp32 projected input (tail beta-mix)
__device__ __half   g_Xh[NN * CD];      // fp16 projected input (SpMM layer-0 in)
__device__ __half   g_H0[NN * CD];      // fp16 layer-0 output
__device__ __half   g_H1[NN * CD];      // fp16 layer-1 output
__device__ uint2    g_ed[TE];           // packed edge: {col | type<<20, w bits}
__device__ int      g_cnt[NN];
__device__ int      g_off[NN + 1];
__device__ int      g_cur[NN];
__device__ int      g_bsum[256];
__device__ int      g_boff[256];
__device__ float    g_filt[LL * CC * TT];

// ---------------- zero counters + softmax over edge types (fused) -----------
__global__ void k_zero(const float* __restrict__ cw) {
    int i = blockIdx.x * blockDim.x + threadIdx.x;
    if (i < NN) g_cnt[i] = 0;
    if (blockIdx.x == 0 && threadIdx.x < LL * CC) {
        const float* p = cw + threadIdx.x * TT;
        float m = p[0];
        for (int t = 1; t < TT; t++) m = fmaxf(m, p[t]);
        float e[TT]; float s = 0.f;
        for (int t = 0; t < TT; t++) { e[t] = __expf(p[t] - m); s += e[t]; }
        float inv = 1.f / s;
        for (int t = 0; t < TT; t++) g_filt[threadIdx.x * TT + t] = e[t] * inv;
    }
}

__global__ void k_hist(const int* __restrict__ ei) {
    int idx = blockIdx.x * blockDim.x + threadIdx.x;
    if (idx >= TE) return;
    int t = idx / EE;
    int e = idx - t * EE;
    int dst = ei[t * 2 * EE + e];
    atomicAdd(&g_cnt[dst], 1);
}

#define SCHUNK 512
#define SNB    196            // ceil(100000/512)

__global__ void k_scan1() {
    __shared__ int s[SCHUNK];
    int tid = threadIdx.x;
    int i = blockIdx.x * SCHUNK + tid;
    int v = (i < NN) ? g_cnt[i] : 0;
    s[tid] = v;
    __syncthreads();
    for (int o = 1; o < SCHUNK; o <<= 1) {
        int t = (tid >= o) ? s[tid - o] : 0;
        __syncthreads();
        s[tid] += t;
        __syncthreads();
    }
    if (i < NN) g_off[i] = s[tid] - v;
    if (tid == SCHUNK - 1) g_bsum[blockIdx.x] = s[tid];
}

__global__ void k_scan2() {
    __shared__ int s[256];
    int tid = threadIdx.x;
    int v = (tid < SNB) ? g_bsum[tid] : 0;
    s[tid] = v;
    __syncthreads();
    for (int o = 1; o < 256; o <<= 1) {
        int t = (tid >= o) ? s[tid - o] : 0;
        __syncthreads();
        s[tid] += t;
        __syncthreads();
    }
    if (tid < SNB) g_boff[tid] = s[tid] - v;
}

__global__ void k_scan3() {
    int tid = threadIdx.x;
    int i = blockIdx.x * SCHUNK + tid;
    if (i < NN) {
        int o = g_off[i] + g_boff[blockIdx.x];
        g_off[i] = o;
        g_cur[i] = o;
    }
    if (blockIdx.x == 0 && tid == 0) g_off[NN] = TE;
}

__global__ void k_scatter(const int* __restrict__ ei, const float* __restrict__ ev) {
    int idx = blockIdx.x * blockDim.x + threadIdx.x;
    if (idx >= TE) return;
    int t = idx / EE;
    int e = idx - t * EE;
    int dst = ei[t * 2 * EE + e];
    int col = ei[t * 2 * EE + EE + e];
    int pos = atomicAdd(&g_cur[dst], 1);
    uint2 rec;
    rec.x = (unsigned)col | ((unsigned)t << 20);
    rec.y = __float_as_uint(ev[idx]);
    g_ed[pos] = rec;
}

// ---------------- input projection: Xp[n][c*64+d] = X[n] @ Ws[c][:,d] --------
#define GBN 32
__global__ void __launch_bounds__(128) k_gemm(const float* __restrict__ X,
                                              const float* __restrict__ Ws) {
    __shared__ float Xs[GBN][WIN];
    int tid = threadIdx.x;
    int n0 = blockIdx.x * GBN;
    for (int idx = tid; idx < GBN * WIN; idx += 128)
        Xs[idx >> 7][idx & 127] = X[(n0 + (idx >> 7)) * WIN + (idx & 127)];
    __syncthreads();

    int c = tid >> 6, d = tid & 63;
    const float* wp = Ws + c * (WIN * DD) + d;
    float acc[GBN];
#pragma unroll
    for (int i = 0; i < GBN; i++) acc[i] = 0.f;

    for (int f = 0; f < WIN; f += 4) {
        float w0 = wp[(f + 0) * DD];
        float w1 = wp[(f + 1) * DD];
        float w2 = wp[(f + 2) * DD];
        float w3 = wp[(f + 3) * DD];
#pragma unroll
        for (int i = 0; i < GBN; i++) {
            float4 x = *(const float4*)&Xs[i][f];
            acc[i] += x.x * w0 + x.y * w1 + x.z * w2 + x.w * w3;
        }
    }
#pragma unroll
    for (int i = 0; i < GBN; i++) {
        g_Xp[(n0 + i) * CD + tid] = acc[i];
        g_Xh[(n0 + i) * CD + tid] = __float2half_rn(acc[i]);
    }
}

// ---------------- SpMM: warp per destination, both channels fused, fp16 in --
__device__ __forceinline__ void gfma(const __half* __restrict__ Hin, unsigned pc,
                                     float f, int off4,
                                     float& ax, float& ay, float& az, float& aw) {
    const uint2 hv = *(const uint2*)(Hin + (size_t)(pc & 0xFFFFFu) * CD + off4);
    float2 p0 = __half22float2(*(const __half2*)&hv.x);
    float2 p1 = __half22float2(*(const __half2*)&hv.y);
    ax += f * p0.x; ay += f * p0.y; az += f * p1.x; aw += f * p1.y;
}

__global__ void __launch_bounds__(256) k_spmm(int layer) {
    const __half* __restrict__ Hin  = (layer == 0) ? g_Xh : g_H0;
    __half* __restrict__       Hout = (layer == 0) ? g_H0 : g_H1;

    __shared__ float fs[CC * TT];
    int tid = threadIdx.x;
    if (tid < CC * TT) fs[tid] = g_filt[layer * CC * TT + tid];
    __syncthreads();

    int wid = (blockIdx.x * blockDim.x + tid) >> 5;
    if (wid >= NN) return;
    int lane = tid & 31;
    int c = lane >> 4;
    const float* fc = fs + c * TT;
    int off4 = lane * 4;

    int i   = g_off[wid];
    int end = g_off[wid + 1];
    float ax = 0.f, ay = 0.f, az = 0.f, aw = 0.f;

    for (; i + 4 <= end; i += 4) {
        uint2 e0 = g_ed[i], e1 = g_ed[i + 1], e2 = g_ed[i + 2], e3 = g_ed[i + 3];
        float f0 = __uint_as_float(e0.y) * fc[e0.x >> 20];
        float f1 = __uint_as_float(e1.y) * fc[e1.x >> 20];
        float f2 = __uint_as_float(e2.y) * fc[e2.x >> 20];
        float f3 = __uint_as_float(e3.y) * fc[e3.x >> 20];
        gfma(Hin, e0.x, f0, off4, ax, ay, az, aw);
        gfma(Hin, e1.x, f1, off4, ax, ay, az, aw);
        gfma(Hin, e2.x, f2, off4, ax, ay, az, aw);
        gfma(Hin, e3.x, f3, off4, ax, ay, az, aw);
    }
    for (; i < end; i++) {
        uint2 e0 = g_ed[i];
        float f0 = __uint_as_float(e0.y) * fc[e0.x >> 20];
        gfma(Hin, e0.x, f0, off4, ax, ay, az, aw);
    }

    __half2 o0 = __floats2half2_rn(ax, ay);
    __half2 o1 = __floats2half2_rn(az, aw);
    uint2 ov;
    ov.x = *(unsigned*)&o0;
    ov.y = *(unsigned*)&o1;
    *(uint2*)(Hout + (size_t)wid * CD + off4) = ov;
}

// ---------------- fused tail at target nodes ---------------------------------
#define TGT 8
__global__ void __launch_bounds__(128) k_tail(const int* __restrict__ targets,
                                              const float* __restrict__ lin1_w,
                                              const float* __restrict__ lin1_b,
                                              const float* __restrict__ lin_w,
                                              const float* __restrict__ lin_b,
                                              float* __restrict__ out) {
    __shared__ float hc[TGT][CD];
    __shared__ float hs[TGT][DD];
    __shared__ int   tg[TGT];
    int tid = threadIdx.x;
    int m0 = blockIdx.x * TGT;
    if (tid < TGT) tg[tid] = targets[m0 + tid];
    __syncthreads();

    for (int idx = tid; idx < TGT * CD; idx += 128) {
        int t = idx >> 7, k = idx & 127;
        size_t p = (size_t)tg[t] * CD + k;
        float v = 0.5f * g_Xp[p] + 0.5f * __half2float(g_H1[p]);
        hc[t][k] = v > 0.f ? v : 0.f;
    }
    __syncthreads();

    int half_ = tid >> 6;
    int d = tid & 63;
    int t0 = half_ * 4;
    float a0 = lin1_b[d], a1 = a0, a2 = a0, a3 = a0;
    for (int k = 0; k < CD; k++) {
        float w = lin1_w[k * DD + d];
        a0 += hc[t0 + 0][k] * w;
        a1 += hc[t0 + 1][k] * w;
        a2 += hc[t0 + 2][k] * w;
        a3 += hc[t0 + 3][k] * w;
    }
    hs[t0 + 0][d] = a0;
    hs[t0 + 1][d] = a1;
    hs[t0 + 2][d] = a2;
    hs[t0 + 3][d] = a3;
    __syncthreads();

    int t = tid >> 4, j = tid & 15;
    float o = lin_b[j];
    for (int dd = 0; dd < DD; dd++)
        o += hs[t][dd] * lin_w[dd * NCLS + j];
    out[(size_t)(m0 + t) * NCLS + j] = o;
}

// ---------------- launcher ---------------------------------------------------
extern "C" void kernel_launch(void* const* d_in, const int* in_sizes, int n_in,
                              void* d_out, int out_size) {
    const float* X      = (const float*)d_in[0];
    const float* ev     = (const float*)d_in[1];
    const float* cw     = (const float*)d_in[2];
    const float* Ws     = (const float*)d_in[3];
    const float* lin1_w = (const float*)d_in[4];
    const float* lin1_b = (const float*)d_in[5];
    const float* lin_w  = (const float*)d_in[6];
    const float* lin_b  = (const float*)d_in[7];
    const int*   ei     = (const int*)d_in[8];
    const int*   tgt    = (const int*)d_in[9];
    float* out          = (float*)d_out;

    k_zero<<<(NN + 255) / 256, 256>>>(cw);
    k_hist<<<(TE + 255) / 256, 256>>>(ei);
    k_scan1<<<SNB, SCHUNK>>>();
    k_scan2<<<1, 256>>>();
    k_scan3<<<SNB, SCHUNK>>>();
    k_scatter<<<(TE + 255) / 256, 256>>>(ei, ev);

    k_gemm<<<NN / GBN, 128>>>(X, Ws);

    k_spmm<<<(NN * 32 + 255) / 256, 256>>>(0);
    k_spmm<<<(NN * 32 + 255) / 256, 256>>>(1);

    k_tail<<<MM / TGT, 128>>>(tgt, lin1_w, lin1_b, lin_w, lin_b, out);
}